// round 11
// baseline (speedup 1.0000x reference)
#include <cuda_runtime.h>
#include <cuda_bf16.h>
#include <cuda_fp16.h>
#include <cstdint>

// RBF causal attention via mma.sync: bf16 split S, row-max-rescaled fp16 PV.
// B=2, H=16, S=2048, D=64, fp32 in/out.

#define B_ 2
#define H_ 16
#define S_ 2048
#define D_ 64
#define SCALE 0.125f
#define NBHS (B_*H_*S_)
#define NBHSD2 (NBHS*32)        // 2-elem vectors per row (D/2 = 32)

// ---- scratch (static device globals; no runtime alloc) ----
__device__ __nv_bfloat162 g_qhi[NBHSD2];
__device__ __nv_bfloat162 g_qlo[NBHSD2];
__device__ __nv_bfloat162 g_khi[NBHSD2];
__device__ __nv_bfloat162 g_klo[NBHSD2];
__device__ __half2        g_vh [NBHSD2];
__device__ float g_qsq[NBHS];
__device__ float g_ksq[NBHS];

// ============================ helpers ============================
__device__ __forceinline__ uint32_t smem_u32(const void* p) {
    uint32_t a;
    asm("{ .reg .u64 t; cvta.to.shared.u64 t, %1; cvt.u32.u64 %0, t; }" : "=r"(a) : "l"(p));
    return a;
}
__device__ __forceinline__ void cp16(uint32_t s, const void* g) {
    asm volatile("cp.async.cg.shared.global [%0], [%1], 16;\n" :: "r"(s), "l"(g));
}
#define CP_COMMIT() asm volatile("cp.async.commit_group;\n" ::: "memory")
template <int N>
__device__ __forceinline__ void cp_wait() {
    asm volatile("cp.async.wait_group %0;\n" :: "n"(N) : "memory");
}
__device__ __forceinline__ void ldsm4(uint32_t r[4], uint32_t a) {
    asm volatile("ldmatrix.sync.aligned.m8n8.x4.shared.b16 {%0,%1,%2,%3}, [%4];\n"
        : "=r"(r[0]), "=r"(r[1]), "=r"(r[2]), "=r"(r[3]) : "r"(a));
}
__device__ __forceinline__ void ldsm4t(uint32_t r[4], uint32_t a) {
    asm volatile("ldmatrix.sync.aligned.m8n8.x4.trans.shared.b16 {%0,%1,%2,%3}, [%4];\n"
        : "=r"(r[0]), "=r"(r[1]), "=r"(r[2]), "=r"(r[3]) : "r"(a));
}
__device__ __forceinline__ void mma_bf16(float c[4], const uint32_t a[4],
                                         uint32_t b0, uint32_t b1) {
    asm volatile("mma.sync.aligned.m16n8k16.row.col.f32.bf16.bf16.f32 "
        "{%0,%1,%2,%3}, {%4,%5,%6,%7}, {%8,%9}, {%0,%1,%2,%3};\n"
        : "+f"(c[0]), "+f"(c[1]), "+f"(c[2]), "+f"(c[3])
        : "r"(a[0]), "r"(a[1]), "r"(a[2]), "r"(a[3]), "r"(b0), "r"(b1));
}
__device__ __forceinline__ void mma_fp16(float c[4], const uint32_t a[4],
                                         uint32_t b0, uint32_t b1) {
    asm volatile("mma.sync.aligned.m16n8k16.row.col.f32.f16.f16.f32 "
        "{%0,%1,%2,%3}, {%4,%5,%6,%7}, {%8,%9}, {%0,%1,%2,%3};\n"
        : "+f"(c[0]), "+f"(c[1]), "+f"(c[2]), "+f"(c[3])
        : "r"(a[0]), "r"(a[1]), "r"(a[2]), "r"(a[3]), "r"(b0), "r"(b1));
}
__device__ __forceinline__ uint32_t h2u(__half2 h) {
    union { __half2 b; uint32_t u; } cv; cv.b = h; return cv.u;
}

// ============================ prepass ============================
__global__ __launch_bounds__(256)
void prep_kernel(const float* __restrict__ q, const float* __restrict__ k,
                 const float* __restrict__ v) {
    int r   = blockIdx.x * 8 + (threadIdx.x >> 5);
    int lid = threadIdx.x & 31;
    size_t e2 = (size_t)r * 32 + lid;

    float2 x = ((const float2*)q)[e2];
    __nv_bfloat162 h = __floats2bfloat162_rn(x.x, x.y);
    float2 hf = __bfloat1622float2(h);
    g_qhi[e2] = h;
    g_qlo[e2] = __floats2bfloat162_rn(x.x - hf.x, x.y - hf.y);
    float s = x.x * x.x + x.y * x.y;
    #pragma unroll
    for (int o = 16; o; o >>= 1) s += __shfl_xor_sync(0xffffffffu, s, o);
    if (!lid) g_qsq[r] = SCALE * s;

    x = ((const float2*)k)[e2];
    h = __floats2bfloat162_rn(x.x, x.y);
    hf = __bfloat1622float2(h);
    g_khi[e2] = h;
    g_klo[e2] = __floats2bfloat162_rn(x.x - hf.x, x.y - hf.y);
    s = x.x * x.x + x.y * x.y;
    #pragma unroll
    for (int o = 16; o; o >>= 1) s += __shfl_xor_sync(0xffffffffu, s, o);
    if (!lid) g_ksq[r] = SCALE * s;

    x = ((const float2*)v)[e2];
    g_vh[e2] = __floats2half2_rn(x.x, x.y);
}

// ============================ main kernel ============================
#define NT 256
#define OFF_Q   0              // Qhi 16KB, Qlo 16KB
#define OFF_KV  32768          // per buf: Khi,Klo,Vh (16KB each)
#define KVSTRIDE 49152
#define OFF_KSQ 131072         // 512B per buf x2
#define OFF_QSQ 132096         // 512B
#define SMEM_BYTES 132608

__global__ __launch_bounds__(NT, 1)
void rbf_mma_kernel(float* __restrict__ out) {
    extern __shared__ char smc[];
    const uint32_t smb = smem_u32(smc);
    const int tid = threadIdx.x, lane = tid & 31, warp = tid >> 5;
    const int bh = blockIdx.y;
    const int qt = (int)gridDim.x - 1 - (int)blockIdx.x;   // heavy tiles first
    const size_t row0q = (size_t)bh * S_ + (size_t)qt * 128;

    // ---- group 0: Q hi/lo + qsq ----
    {
        const char* gq0 = (const char*)(g_qhi + row0q * 32);
        const char* gq1 = (const char*)(g_qlo + row0q * 32);
        #pragma unroll
        for (int i = 0; i < 4; i++) {
            int idx = tid + NT * i;              // 0..1023 16B chunks
            int row = idx >> 3, c = idx & 7;
            uint32_t rel = row * 128 + ((c ^ (row & 7)) << 4);
            cp16(smb + OFF_Q + rel, gq0 + idx * 16);
            cp16(smb + OFF_Q + 16384 + rel, gq1 + idx * 16);
        }
        if (tid < 32) cp16(smb + OFF_QSQ + tid * 16, g_qsq + row0q + tid * 4);
    }

    auto prefetch = [&](int kt2, int buf) {
        const size_t row0k = (size_t)bh * S_ + (size_t)kt2 * 128;
        const char* ga[3] = { (const char*)(g_khi + row0k * 32),
                              (const char*)(g_klo + row0k * 32),
                              (const char*)(g_vh  + row0k * 32) };
        const uint32_t bb = smb + OFF_KV + buf * KVSTRIDE;
        #pragma unroll
        for (int a = 0; a < 3; a++)
            #pragma unroll
            for (int i = 0; i < 4; i++) {
                int idx = tid + NT * i;
                int row = idx >> 3, c = idx & 7;
                cp16(bb + a * 16384 + row * 128 + ((c ^ (row & 7)) << 4), ga[a] + idx * 16);
            }
        if (tid < 32) cp16(smb + OFF_KSQ + buf * 512 + tid * 16, g_ksq + row0k + tid * 4);
    };

    prefetch(0, 0);
    CP_COMMIT();

    // per-thread fragment coordinates
    const int g8 = lane >> 2;                    // 0..7
    const int t2 = (lane & 3) * 2;               // 0,2,4,6
    const int arow = warp * 16 + (lane & 15);    // A (Q) ldmatrix row
    const int acb  = (lane >> 4) * 16;           // A k-byte half
    const int brow = (lane & 7) + (lane >> 4) * 8;       // K ldmatrix row offset
    const int bcb  = ((lane >> 3) & 1) * 16;             // K k-byte half
    const int vrow = (lane & 7) + ((lane >> 3) & 1) * 8; // V ldmatrix row offset
    const int vcb  = (lane >> 4) * 16;                   // V d-byte half

    uint32_t qh[4][4], ql[4][4];                 // Q frags, loaded at kt==0
    float co[8][4];
    #pragma unroll
    for (int i = 0; i < 8; i++) { co[i][0] = co[i][1] = co[i][2] = co[i][3] = 0.f; }
    float m0r = -1e30f, m1r = -1e30f;            // running row maxima (rows m0, m0+8)

    const float* qsq_s = (const float*)(smc + OFF_QSQ);

    for (int kt = 0; kt <= qt; kt++) {
        const int buf = kt & 1;
        if (kt < qt) { prefetch(kt + 1, buf ^ 1); CP_COMMIT(); cp_wait<1>(); }
        else         { cp_wait<0>(); }
        __syncthreads();

        const uint32_t kvb  = smb + OFF_KV + buf * KVSTRIDE;
        const uint32_t khib = kvb;
        const uint32_t klob = kvb + 16384;
        const uint32_t vhb  = kvb + 32768;
        const float* ksq_s = (const float*)(smc + OFF_KSQ + buf * 512);

        if (kt == 0) {
            #pragma unroll
            for (int kc = 0; kc < 4; kc++) {
                uint32_t kb = kc * 32 + acb;
                uint32_t addr = smb + OFF_Q + arow * 128 + ((((kb >> 4)) ^ (arow & 7)) << 4);
                ldsm4(qh[kc], addr);
                ldsm4(ql[kc], addr + 16384);
            }
        }

        const bool diag = (kt == qt);
        const int m0 = warp * 16 + g8;           // local rows m0, m0+8
        const float qs0 = qsq_s[m0], qs1 = qsq_s[m0 + 8];

        // ---- S = Q K^T (3 split terms), warp stripe 16 x 128 ----
        float cs[16][4];
        #pragma unroll
        for (int i = 0; i < 16; i++) { cs[i][0] = cs[i][1] = cs[i][2] = cs[i][3] = 0.f; }

        #pragma unroll
        for (int kc = 0; kc < 4; kc++) {
            uint32_t kb = kc * 32 + bcb;
            #pragma unroll
            for (int nf2 = 0; nf2 < 8; nf2++) {
                if (diag && nf2 > warp) break;          // fully-masked key chunk
                int key = nf2 * 16 + brow;
                uint32_t rel = key * 128 + (((kb >> 4) ^ (key & 7)) << 4);
                uint32_t bk[4];
                ldsm4(bk, khib + rel);                  // Khi
                mma_bf16(cs[2 * nf2],     qh[kc], bk[0], bk[1]);
                mma_bf16(cs[2 * nf2 + 1], qh[kc], bk[2], bk[3]);
                mma_bf16(cs[2 * nf2],     ql[kc], bk[0], bk[1]);
                mma_bf16(cs[2 * nf2 + 1], ql[kc], bk[2], bk[3]);
                ldsm4(bk, klob + rel);                  // Klo
                mma_bf16(cs[2 * nf2],     qh[kc], bk[0], bk[1]);
                mma_bf16(cs[2 * nf2 + 1], qh[kc], bk[2], bk[3]);
            }
        }

        // ---- pass A: logits + per-row tile max ----
        float t0 = -1e30f, t1 = -1e30f;
        #pragma unroll
        for (int nf = 0; nf < 16; nf++) {
            if (diag && nf >= 2 * warp + 2) break;
            const int n0 = nf * 8 + t2;
            const float2 kk = *(const float2*)&ksq_s[n0];
            float l0 = fmaf(0.25f, cs[nf][0], -(qs0 + kk.x));
            float l1 = fmaf(0.25f, cs[nf][1], -(qs0 + kk.y));
            float l2 = fmaf(0.25f, cs[nf][2], -(qs1 + kk.x));
            float l3 = fmaf(0.25f, cs[nf][3], -(qs1 + kk.y));
            if (diag) {
                if (n0     > m0)     l0 = -1e30f;
                if (n0 + 1 > m0)     l1 = -1e30f;
                if (n0     > m0 + 8) l2 = -1e30f;
                if (n0 + 1 > m0 + 8) l3 = -1e30f;
            }
            cs[nf][0] = l0; cs[nf][1] = l1; cs[nf][2] = l2; cs[nf][3] = l3;
            t0 = fmaxf(t0, fmaxf(l0, l1));
            t1 = fmaxf(t1, fmaxf(l2, l3));
        }
        t0 = fmaxf(t0, __shfl_xor_sync(0xffffffffu, t0, 1));
        t0 = fmaxf(t0, __shfl_xor_sync(0xffffffffu, t0, 2));
        t1 = fmaxf(t1, __shfl_xor_sync(0xffffffffu, t1, 1));
        t1 = fmaxf(t1, __shfl_xor_sync(0xffffffffu, t1, 2));
        const float mn0 = fmaxf(m0r, t0), mn1 = fmaxf(m1r, t1);
        const float a0 = __expf(m0r - mn0), a1 = __expf(m1r - mn1);
        m0r = mn0; m1r = mn1;
        #pragma unroll
        for (int i = 0; i < 8; i++) {
            co[i][0] *= a0; co[i][1] *= a0; co[i][2] *= a1; co[i][3] *= a1;
        }

        // ---- pass B: p = exp(l - m), fp16 hi/lo split, PV (2 terms) ----
        #pragma unroll
        for (int kc = 0; kc < 8; kc++) {
            if (diag && kc > warp) break;               // fully-masked key chunk
            uint32_t ahh[4], ahl[4];
            #pragma unroll
            for (int h = 0; h < 2; h++) {
                const int nf = 2 * kc + h;
                float p00 = __expf(cs[nf][0] - mn0);
                float p01 = __expf(cs[nf][1] - mn0);
                float p10 = __expf(cs[nf][2] - mn1);
                float p11 = __expf(cs[nf][3] - mn1);
                __half2 h0 = __floats2half2_rn(p00, p01);
                __half2 h1 = __floats2half2_rn(p10, p11);
                float2 f0 = __half22float2(h0);
                float2 f1 = __half22float2(h1);
                ahh[2 * h]     = h2u(h0);
                ahh[2 * h + 1] = h2u(h1);
                ahl[2 * h]     = h2u(__floats2half2_rn(p00 - f0.x, p01 - f0.y));
                ahl[2 * h + 1] = h2u(__floats2half2_rn(p10 - f1.x, p11 - f1.y));
            }
            const int key = kc * 16 + vrow;
            #pragma unroll
            for (int df2 = 0; df2 < 4; df2++) {
                uint32_t db = df2 * 32 + vcb;
                uint32_t rel = key * 128 + (((db >> 4) ^ (key & 7)) << 4);
                uint32_t bv[4];
                ldsm4t(bv, vhb + rel);                  // V fp16
                mma_fp16(co[2 * df2],     ahh, bv[0], bv[1]);
                mma_fp16(co[2 * df2 + 1], ahh, bv[2], bv[3]);
                mma_fp16(co[2 * df2],     ahl, bv[0], bv[1]);
                mma_fp16(co[2 * df2 + 1], ahl, bv[2], bv[3]);
            }
        }
        __syncthreads();
    }

    // ---- write output: out = co * exp(m) ----
    const float e0 = __expf(m0r), e1 = __expf(m1r);
    const size_t r0 = row0q + warp * 16 + g8;
    const size_t r1 = r0 + 8;
    #pragma unroll
    for (int nf = 0; nf < 8; nf++) {
        const int d = nf * 8 + t2;
        *(float2*)&out[r0 * D_ + d] = make_float2(co[nf][0] * e0, co[nf][1] * e0);
        *(float2*)&out[r1 * D_ + d] = make_float2(co[nf][2] * e1, co[nf][3] * e1);
    }
}

extern "C" void kernel_launch(void* const* d_in, const int* in_sizes, int n_in,
                              void* d_out, int out_size) {
    const float* q = (const float*)d_in[0];
    const float* k = (const float*)d_in[1];
    const float* v = (const float*)d_in[2];
    float* out = (float*)d_out;

    prep_kernel<<<NBHS / 8, 256>>>(q, k, v);

    cudaFuncSetAttribute(rbf_mma_kernel,
                         cudaFuncAttributeMaxDynamicSharedMemorySize, SMEM_BYTES);
    dim3 grid(S_ / 128, B_ * H_);
    rbf_mma_kernel<<<grid, NT, SMEM_BYTES>>>(out);
}

// round 12
// speedup vs baseline: 1.1498x; 1.1498x over previous
#include <cuda_runtime.h>
#include <cuda_bf16.h>
#include <cuda_fp16.h>
#include <cstdint>

// RBF causal attention via mma.sync: bf16 split S, row-max-rescaled single-fp16 PV.
// log2-domain exponentials. B=2, H=16, S=2048, D=64, fp32 in/out.

#define B_ 2
#define H_ 16
#define S_ 2048
#define D_ 64
#define SCALE 0.125f
#define LOG2E 1.4426950408889634f
#define L2SCALE (0.25f * LOG2E)
#define NBHS (B_*H_*S_)
#define NBHSD2 (NBHS*32)        // 2-elem vectors per row (D/2 = 32)

// ---- scratch (static device globals; no runtime alloc) ----
__device__ __nv_bfloat162 g_qhi[NBHSD2];
__device__ __nv_bfloat162 g_qlo[NBHSD2];
__device__ __nv_bfloat162 g_khi[NBHSD2];
__device__ __nv_bfloat162 g_klo[NBHSD2];
__device__ __half2        g_vh [NBHSD2];
__device__ float g_qsq[NBHS];   // in log2e units
__device__ float g_ksq[NBHS];   // in log2e units

// ============================ helpers ============================
__device__ __forceinline__ uint32_t smem_u32(const void* p) {
    uint32_t a;
    asm("{ .reg .u64 t; cvta.to.shared.u64 t, %1; cvt.u32.u64 %0, t; }" : "=r"(a) : "l"(p));
    return a;
}
__device__ __forceinline__ void cp16(uint32_t s, const void* g) {
    asm volatile("cp.async.cg.shared.global [%0], [%1], 16;\n" :: "r"(s), "l"(g));
}
#define CP_COMMIT() asm volatile("cp.async.commit_group;\n" ::: "memory")
template <int N>
__device__ __forceinline__ void cp_wait() {
    asm volatile("cp.async.wait_group %0;\n" :: "n"(N) : "memory");
}
__device__ __forceinline__ void ldsm4(uint32_t r[4], uint32_t a) {
    asm volatile("ldmatrix.sync.aligned.m8n8.x4.shared.b16 {%0,%1,%2,%3}, [%4];\n"
        : "=r"(r[0]), "=r"(r[1]), "=r"(r[2]), "=r"(r[3]) : "r"(a));
}
__device__ __forceinline__ void ldsm4t(uint32_t r[4], uint32_t a) {
    asm volatile("ldmatrix.sync.aligned.m8n8.x4.trans.shared.b16 {%0,%1,%2,%3}, [%4];\n"
        : "=r"(r[0]), "=r"(r[1]), "=r"(r[2]), "=r"(r[3]) : "r"(a));
}
__device__ __forceinline__ void mma_bf16(float c[4], const uint32_t a[4],
                                         uint32_t b0, uint32_t b1) {
    asm volatile("mma.sync.aligned.m16n8k16.row.col.f32.bf16.bf16.f32 "
        "{%0,%1,%2,%3}, {%4,%5,%6,%7}, {%8,%9}, {%0,%1,%2,%3};\n"
        : "+f"(c[0]), "+f"(c[1]), "+f"(c[2]), "+f"(c[3])
        : "r"(a[0]), "r"(a[1]), "r"(a[2]), "r"(a[3]), "r"(b0), "r"(b1));
}
__device__ __forceinline__ void mma_fp16(float c[4], const uint32_t a[4],
                                         uint32_t b0, uint32_t b1) {
    asm volatile("mma.sync.aligned.m16n8k16.row.col.f32.f16.f16.f32 "
        "{%0,%1,%2,%3}, {%4,%5,%6,%7}, {%8,%9}, {%0,%1,%2,%3};\n"
        : "+f"(c[0]), "+f"(c[1]), "+f"(c[2]), "+f"(c[3])
        : "r"(a[0]), "r"(a[1]), "r"(a[2]), "r"(a[3]), "r"(b0), "r"(b1));
}
__device__ __forceinline__ uint32_t h2u(__half2 h) {
    union { __half2 b; uint32_t u; } cv; cv.b = h; return cv.u;
}

// ============================ prepass ============================
__global__ __launch_bounds__(256)
void prep_kernel(const float* __restrict__ q, const float* __restrict__ k,
                 const float* __restrict__ v) {
    int r   = blockIdx.x * 8 + (threadIdx.x >> 5);
    int lid = threadIdx.x & 31;
    size_t e2 = (size_t)r * 32 + lid;

    float2 x = ((const float2*)q)[e2];
    __nv_bfloat162 h = __floats2bfloat162_rn(x.x, x.y);
    float2 hf = __bfloat1622float2(h);
    g_qhi[e2] = h;
    g_qlo[e2] = __floats2bfloat162_rn(x.x - hf.x, x.y - hf.y);
    float s = x.x * x.x + x.y * x.y;
    #pragma unroll
    for (int o = 16; o; o >>= 1) s += __shfl_xor_sync(0xffffffffu, s, o);
    if (!lid) g_qsq[r] = SCALE * LOG2E * s;

    x = ((const float2*)k)[e2];
    h = __floats2bfloat162_rn(x.x, x.y);
    hf = __bfloat1622float2(h);
    g_khi[e2] = h;
    g_klo[e2] = __floats2bfloat162_rn(x.x - hf.x, x.y - hf.y);
    s = x.x * x.x + x.y * x.y;
    #pragma unroll
    for (int o = 16; o; o >>= 1) s += __shfl_xor_sync(0xffffffffu, s, o);
    if (!lid) g_ksq[r] = SCALE * LOG2E * s;

    x = ((const float2*)v)[e2];
    g_vh[e2] = __floats2half2_rn(x.x, x.y);
}

// ============================ main kernel ============================
#define NT 256
#define OFF_Q   0              // Qhi 16KB, Qlo 16KB
#define OFF_KV  32768          // per buf: Khi,Klo,Vh (16KB each)
#define KVSTRIDE 49152
#define OFF_KSQ 131072         // 512B per buf x2
#define OFF_QSQ 132096         // 512B
#define SMEM_BYTES 132608

__global__ __launch_bounds__(NT, 1)
void rbf_mma_kernel(float* __restrict__ out) {
    extern __shared__ char smc[];
    const uint32_t smb = smem_u32(smc);
    const int tid = threadIdx.x, lane = tid & 31, warp = tid >> 5;
    const int bh = blockIdx.y;
    const int qt = (int)gridDim.x - 1 - (int)blockIdx.x;   // heavy tiles first
    const size_t row0q = (size_t)bh * S_ + (size_t)qt * 128;

    // ---- group 0: Q hi/lo + qsq ----
    {
        const char* gq0 = (const char*)(g_qhi + row0q * 32);
        const char* gq1 = (const char*)(g_qlo + row0q * 32);
        #pragma unroll
        for (int i = 0; i < 4; i++) {
            int idx = tid + NT * i;              // 0..1023 16B chunks
            int row = idx >> 3, c = idx & 7;
            uint32_t rel = row * 128 + ((c ^ (row & 7)) << 4);
            cp16(smb + OFF_Q + rel, gq0 + idx * 16);
            cp16(smb + OFF_Q + 16384 + rel, gq1 + idx * 16);
        }
        if (tid < 32) cp16(smb + OFF_QSQ + tid * 16, g_qsq + row0q + tid * 4);
    }

    auto prefetch = [&](int kt2, int buf) {
        const size_t row0k = (size_t)bh * S_ + (size_t)kt2 * 128;
        const char* ga[3] = { (const char*)(g_khi + row0k * 32),
                              (const char*)(g_klo + row0k * 32),
                              (const char*)(g_vh  + row0k * 32) };
        const uint32_t bb = smb + OFF_KV + buf * KVSTRIDE;
        #pragma unroll
        for (int a = 0; a < 3; a++)
            #pragma unroll
            for (int i = 0; i < 4; i++) {
                int idx = tid + NT * i;
                int row = idx >> 3, c = idx & 7;
                cp16(bb + a * 16384 + row * 128 + ((c ^ (row & 7)) << 4), ga[a] + idx * 16);
            }
        if (tid < 32) cp16(smb + OFF_KSQ + buf * 512 + tid * 16, g_ksq + row0k + tid * 4);
    };

    prefetch(0, 0);
    CP_COMMIT();

    // per-thread fragment coordinates
    const int g8 = lane >> 2;                    // 0..7
    const int t2 = (lane & 3) * 2;               // 0,2,4,6
    const int arow = warp * 16 + (lane & 15);    // A (Q) ldmatrix row
    const int acb  = (lane >> 4) * 16;           // A k-byte half
    const int brow = (lane & 7) + (lane >> 4) * 8;       // K ldmatrix row offset
    const int bcb  = ((lane >> 3) & 1) * 16;             // K k-byte half
    const int vrow = (lane & 7) + ((lane >> 3) & 1) * 8; // V ldmatrix row offset
    const int vcb  = (lane >> 4) * 16;                   // V d-byte half

    uint32_t qh[4][4], ql[4][4];                 // Q frags, loaded at kt==0
    float co[8][4];
    #pragma unroll
    for (int i = 0; i < 8; i++) { co[i][0] = co[i][1] = co[i][2] = co[i][3] = 0.f; }
    float m0r = -1e30f, m1r = -1e30f;            // running row maxima (log2 units)

    const float* qsq_s = (const float*)(smc + OFF_QSQ);

    for (int kt = 0; kt <= qt; kt++) {
        const int buf = kt & 1;
        if (kt < qt) { prefetch(kt + 1, buf ^ 1); CP_COMMIT(); cp_wait<1>(); }
        else         { cp_wait<0>(); }
        __syncthreads();

        const uint32_t kvb  = smb + OFF_KV + buf * KVSTRIDE;
        const uint32_t khib = kvb;
        const uint32_t klob = kvb + 16384;
        const uint32_t vhb  = kvb + 32768;
        const float* ksq_s = (const float*)(smc + OFF_KSQ + buf * 512);

        if (kt == 0) {
            #pragma unroll
            for (int kc = 0; kc < 4; kc++) {
                uint32_t kb = kc * 32 + acb;
                uint32_t addr = smb + OFF_Q + arow * 128 + ((((kb >> 4)) ^ (arow & 7)) << 4);
                ldsm4(qh[kc], addr);
                ldsm4(ql[kc], addr + 16384);
            }
        }

        const bool diag = (kt == qt);
        const int m0 = warp * 16 + g8;           // local rows m0, m0+8
        const float qs0 = qsq_s[m0], qs1 = qsq_s[m0 + 8];

        // ---- S = Q K^T (3 split terms), warp stripe 16 x 128 ----
        float cs[16][4];
        #pragma unroll
        for (int i = 0; i < 16; i++) { cs[i][0] = cs[i][1] = cs[i][2] = cs[i][3] = 0.f; }

        #pragma unroll
        for (int kc = 0; kc < 4; kc++) {
            uint32_t kb = kc * 32 + bcb;
            #pragma unroll
            for (int nf2 = 0; nf2 < 8; nf2++) {
                if (diag && nf2 > warp) break;          // fully-masked key chunk
                int key = nf2 * 16 + brow;
                uint32_t rel = key * 128 + (((kb >> 4) ^ (key & 7)) << 4);
                uint32_t bkh[4], bkl[4];
                ldsm4(bkh, khib + rel);                 // Khi
                ldsm4(bkl, klob + rel);                 // Klo (issued before MMAs)
                mma_bf16(cs[2 * nf2],     qh[kc], bkh[0], bkh[1]);
                mma_bf16(cs[2 * nf2 + 1], qh[kc], bkh[2], bkh[3]);
                mma_bf16(cs[2 * nf2],     ql[kc], bkh[0], bkh[1]);
                mma_bf16(cs[2 * nf2 + 1], ql[kc], bkh[2], bkh[3]);
                mma_bf16(cs[2 * nf2],     qh[kc], bkl[0], bkl[1]);
                mma_bf16(cs[2 * nf2 + 1], qh[kc], bkl[2], bkl[3]);
            }
        }

        // ---- pass A: log2-logits + per-row tile max ----
        float t0 = -1e30f, t1 = -1e30f;
        #pragma unroll
        for (int nf = 0; nf < 16; nf++) {
            if (diag && nf >= 2 * warp + 2) break;
            const int n0 = nf * 8 + t2;
            const float2 kk = *(const float2*)&ksq_s[n0];
            float l0 = fmaf(L2SCALE, cs[nf][0], -(qs0 + kk.x));
            float l1 = fmaf(L2SCALE, cs[nf][1], -(qs0 + kk.y));
            float l2 = fmaf(L2SCALE, cs[nf][2], -(qs1 + kk.x));
            float l3 = fmaf(L2SCALE, cs[nf][3], -(qs1 + kk.y));
            if (diag) {
                if (n0     > m0)     l0 = -1e30f;
                if (n0 + 1 > m0)     l1 = -1e30f;
                if (n0     > m0 + 8) l2 = -1e30f;
                if (n0 + 1 > m0 + 8) l3 = -1e30f;
            }
            cs[nf][0] = l0; cs[nf][1] = l1; cs[nf][2] = l2; cs[nf][3] = l3;
            t0 = fmaxf(t0, fmaxf(l0, l1));
            t1 = fmaxf(t1, fmaxf(l2, l3));
        }
        t0 = fmaxf(t0, __shfl_xor_sync(0xffffffffu, t0, 1));
        t0 = fmaxf(t0, __shfl_xor_sync(0xffffffffu, t0, 2));
        t1 = fmaxf(t1, __shfl_xor_sync(0xffffffffu, t1, 1));
        t1 = fmaxf(t1, __shfl_xor_sync(0xffffffffu, t1, 2));
        const float mn0 = fmaxf(m0r, t0), mn1 = fmaxf(m1r, t1);
        const float a0 = exp2f(m0r - mn0), a1 = exp2f(m1r - mn1);
        m0r = mn0; m1r = mn1;
        #pragma unroll
        for (int i = 0; i < 8; i++) {
            co[i][0] *= a0; co[i][1] *= a0; co[i][2] *= a1; co[i][3] *= a1;
        }

        // ---- pass B: p = exp2(l - m) fp16, PV single term ----
        #pragma unroll
        for (int kc = 0; kc < 8; kc++) {
            if (diag && kc > warp) break;               // fully-masked key chunk
            uint32_t ah[4];
            #pragma unroll
            for (int h = 0; h < 2; h++) {
                const int nf = 2 * kc + h;
                float p00 = exp2f(cs[nf][0] - mn0);
                float p01 = exp2f(cs[nf][1] - mn0);
                float p10 = exp2f(cs[nf][2] - mn1);
                float p11 = exp2f(cs[nf][3] - mn1);
                ah[2 * h]     = h2u(__floats2half2_rn(p00, p01));
                ah[2 * h + 1] = h2u(__floats2half2_rn(p10, p11));
            }
            const int key = kc * 16 + vrow;
            #pragma unroll
            for (int df2 = 0; df2 < 4; df2++) {
                uint32_t db = df2 * 32 + vcb;
                uint32_t rel = key * 128 + (((db >> 4) ^ (key & 7)) << 4);
                uint32_t bv[4];
                ldsm4t(bv, vhb + rel);                  // V fp16
                mma_fp16(co[2 * df2],     ah, bv[0], bv[1]);
                mma_fp16(co[2 * df2 + 1], ah, bv[2], bv[3]);
            }
        }
        __syncthreads();
    }

    // ---- write output: out = co * exp2(m) ----
    const float e0 = exp2f(m0r), e1 = exp2f(m1r);
    const size_t r0 = row0q + warp * 16 + g8;
    const size_t r1 = r0 + 8;
    #pragma unroll
    for (int nf = 0; nf < 8; nf++) {
        const int d = nf * 8 + t2;
        *(float2*)&out[r0 * D_ + d] = make_float2(co[nf][0] * e0, co[nf][1] * e0);
        *(float2*)&out[r1 * D_ + d] = make_float2(co[nf][2] * e1, co[nf][3] * e1);
    }
}

extern "C" void kernel_launch(void* const* d_in, const int* in_sizes, int n_in,
                              void* d_out, int out_size) {
    const float* q = (const float*)d_in[0];
    const float* k = (const float*)d_in[1];
    const float* v = (const float*)d_in[2];
    float* out = (float*)d_out;

    prep_kernel<<<NBHS / 8, 256>>>(q, k, v);

    cudaFuncSetAttribute(rbf_mma_kernel,
                         cudaFuncAttributeMaxDynamicSharedMemorySize, SMEM_BYTES);
    dim3 grid(S_ / 128, B_ * H_);
    rbf_mma_kernel<<<grid, NT, SMEM_BYTES>>>(out);
}

// round 13
// speedup vs baseline: 1.2003x; 1.0439x over previous
#include <cuda_runtime.h>
#include <cuda_bf16.h>
#include <cuda_fp16.h>
#include <cstdint>

// RBF causal attention via mma.sync: bf16 split S, half-tile online max,
// ex2.f16x2 epilogue, single-fp16 PV. B=2, H=16, S=2048, D=64, fp32 in/out.

#define B_ 2
#define H_ 16
#define S_ 2048
#define D_ 64
#define SCALE 0.125f
#define LOG2E 1.4426950408889634f
#define L2SCALE (0.25f * LOG2E)
#define NBHS (B_*H_*S_)
#define NBHSD2 (NBHS*32)        // 2-elem vectors per row (D/2 = 32)

// ---- scratch (static device globals; no runtime alloc) ----
__device__ __nv_bfloat162 g_qhi[NBHSD2];
__device__ __nv_bfloat162 g_qlo[NBHSD2];
__device__ __nv_bfloat162 g_khi[NBHSD2];
__device__ __nv_bfloat162 g_klo[NBHSD2];
__device__ __half2        g_vh [NBHSD2];
__device__ float g_qsq[NBHS];   // in log2e units
__device__ float g_ksq[NBHS];   // in log2e units

// ============================ helpers ============================
__device__ __forceinline__ uint32_t smem_u32(const void* p) {
    uint32_t a;
    asm("{ .reg .u64 t; cvta.to.shared.u64 t, %1; cvt.u32.u64 %0, t; }" : "=r"(a) : "l"(p));
    return a;
}
__device__ __forceinline__ void cp16(uint32_t s, const void* g) {
    asm volatile("cp.async.cg.shared.global [%0], [%1], 16;\n" :: "r"(s), "l"(g));
}
#define CP_COMMIT() asm volatile("cp.async.commit_group;\n" ::: "memory")
template <int N>
__device__ __forceinline__ void cp_wait() {
    asm volatile("cp.async.wait_group %0;\n" :: "n"(N) : "memory");
}
__device__ __forceinline__ void ldsm4(uint32_t r[4], uint32_t a) {
    asm volatile("ldmatrix.sync.aligned.m8n8.x4.shared.b16 {%0,%1,%2,%3}, [%4];\n"
        : "=r"(r[0]), "=r"(r[1]), "=r"(r[2]), "=r"(r[3]) : "r"(a));
}
__device__ __forceinline__ void ldsm4t(uint32_t r[4], uint32_t a) {
    asm volatile("ldmatrix.sync.aligned.m8n8.x4.trans.shared.b16 {%0,%1,%2,%3}, [%4];\n"
        : "=r"(r[0]), "=r"(r[1]), "=r"(r[2]), "=r"(r[3]) : "r"(a));
}
__device__ __forceinline__ void mma_bf16(float c[4], const uint32_t a[4],
                                         uint32_t b0, uint32_t b1) {
    asm volatile("mma.sync.aligned.m16n8k16.row.col.f32.bf16.bf16.f32 "
        "{%0,%1,%2,%3}, {%4,%5,%6,%7}, {%8,%9}, {%0,%1,%2,%3};\n"
        : "+f"(c[0]), "+f"(c[1]), "+f"(c[2]), "+f"(c[3])
        : "r"(a[0]), "r"(a[1]), "r"(a[2]), "r"(a[3]), "r"(b0), "r"(b1));
}
__device__ __forceinline__ void mma_fp16(float c[4], const uint32_t a[4],
                                         uint32_t b0, uint32_t b1) {
    asm volatile("mma.sync.aligned.m16n8k16.row.col.f32.f16.f16.f32 "
        "{%0,%1,%2,%3}, {%4,%5,%6,%7}, {%8,%9}, {%0,%1,%2,%3};\n"
        : "+f"(c[0]), "+f"(c[1]), "+f"(c[2]), "+f"(c[3])
        : "r"(a[0]), "r"(a[1]), "r"(a[2]), "r"(a[3]), "r"(b0), "r"(b1));
}
// pack 2 f32 -> f16x2 (lo = x0), then 2^x elementwise on MUFU (one op per pair)
__device__ __forceinline__ uint32_t exp2_f16x2(float x0, float x1) {
    uint32_t c, r;
    asm("cvt.rn.f16x2.f32 %0, %1, %2;" : "=r"(c) : "f"(x1), "f"(x0));
    asm("ex2.approx.f16x2 %0, %1;" : "=r"(r) : "r"(c));
    return r;
}

// ============================ prepass ============================
__global__ __launch_bounds__(256)
void prep_kernel(const float* __restrict__ q, const float* __restrict__ k,
                 const float* __restrict__ v) {
    int r   = blockIdx.x * 8 + (threadIdx.x >> 5);
    int lid = threadIdx.x & 31;
    size_t e2 = (size_t)r * 32 + lid;

    float2 x = ((const float2*)q)[e2];
    __nv_bfloat162 h = __floats2bfloat162_rn(x.x, x.y);
    float2 hf = __bfloat1622float2(h);
    g_qhi[e2] = h;
    g_qlo[e2] = __floats2bfloat162_rn(x.x - hf.x, x.y - hf.y);
    float s = x.x * x.x + x.y * x.y;
    #pragma unroll
    for (int o = 16; o; o >>= 1) s += __shfl_xor_sync(0xffffffffu, s, o);
    if (!lid) g_qsq[r] = SCALE * LOG2E * s;

    x = ((const float2*)k)[e2];
    h = __floats2bfloat162_rn(x.x, x.y);
    hf = __bfloat1622float2(h);
    g_khi[e2] = h;
    g_klo[e2] = __floats2bfloat162_rn(x.x - hf.x, x.y - hf.y);
    s = x.x * x.x + x.y * x.y;
    #pragma unroll
    for (int o = 16; o; o >>= 1) s += __shfl_xor_sync(0xffffffffu, s, o);
    if (!lid) g_ksq[r] = SCALE * LOG2E * s;

    x = ((const float2*)v)[e2];
    g_vh[e2] = __floats2half2_rn(x.x, x.y);
}

// ============================ main kernel ============================
#define NT 256
#define OFF_Q   0              // Qhi 16KB, Qlo 16KB
#define OFF_KV  32768          // per buf: Khi,Klo,Vh (16KB each)
#define KVSTRIDE 49152
#define OFF_KSQ 131072         // 512B per buf x2
#define OFF_QSQ 132096         // 512B
#define SMEM_BYTES 132608

__global__ __launch_bounds__(NT, 1)
void rbf_mma_kernel(float* __restrict__ out) {
    extern __shared__ char smc[];
    const uint32_t smb = smem_u32(smc);
    const int tid = threadIdx.x, lane = tid & 31, warp = tid >> 5;
    const int bh = blockIdx.y;
    const int qt = (int)gridDim.x - 1 - (int)blockIdx.x;   // heavy tiles first
    const size_t row0q = (size_t)bh * S_ + (size_t)qt * 128;

    // ---- group 0: Q hi/lo + qsq ----
    {
        const char* gq0 = (const char*)(g_qhi + row0q * 32);
        const char* gq1 = (const char*)(g_qlo + row0q * 32);
        #pragma unroll
        for (int i = 0; i < 4; i++) {
            int idx = tid + NT * i;              // 0..1023 16B chunks
            int row = idx >> 3, c = idx & 7;
            uint32_t rel = row * 128 + ((c ^ (row & 7)) << 4);
            cp16(smb + OFF_Q + rel, gq0 + idx * 16);
            cp16(smb + OFF_Q + 16384 + rel, gq1 + idx * 16);
        }
        if (tid < 32) cp16(smb + OFF_QSQ + tid * 16, g_qsq + row0q + tid * 4);
    }

    auto prefetch = [&](int kt2, int buf) {
        const size_t row0k = (size_t)bh * S_ + (size_t)kt2 * 128;
        const char* ga[3] = { (const char*)(g_khi + row0k * 32),
                              (const char*)(g_klo + row0k * 32),
                              (const char*)(g_vh  + row0k * 32) };
        const uint32_t bb = smb + OFF_KV + buf * KVSTRIDE;
        #pragma unroll
        for (int a = 0; a < 3; a++)
            #pragma unroll
            for (int i = 0; i < 4; i++) {
                int idx = tid + NT * i;
                int row = idx >> 3, c = idx & 7;
                cp16(bb + a * 16384 + row * 128 + ((c ^ (row & 7)) << 4), ga[a] + idx * 16);
            }
        if (tid < 32) cp16(smb + OFF_KSQ + buf * 512 + tid * 16, g_ksq + row0k + tid * 4);
    };

    prefetch(0, 0);
    CP_COMMIT();

    // per-thread fragment coordinates
    const int g8 = lane >> 2;                    // 0..7
    const int t2 = (lane & 3) * 2;               // 0,2,4,6
    const int arow = warp * 16 + (lane & 15);    // A (Q) ldmatrix row
    const int acb  = (lane >> 4) * 16;           // A k-byte half
    const int brow = (lane & 7) + (lane >> 4) * 8;       // K ldmatrix row offset
    const int bcb  = ((lane >> 3) & 1) * 16;             // K k-byte half
    const int vrow = (lane & 7) + ((lane >> 3) & 1) * 8; // V ldmatrix row offset
    const int vcb  = (lane >> 4) * 16;                   // V d-byte half

    uint32_t qh[4][4], ql[4][4];                 // Q frags, loaded at kt==0
    float co[8][4];
    #pragma unroll
    for (int i = 0; i < 8; i++) { co[i][0] = co[i][1] = co[i][2] = co[i][3] = 0.f; }
    float m0r = -1e30f, m1r = -1e30f;            // running row maxima (log2 units)

    const float* qsq_s = (const float*)(smc + OFF_QSQ);

    for (int kt = 0; kt <= qt; kt++) {
        const int buf = kt & 1;
        if (kt < qt) { prefetch(kt + 1, buf ^ 1); CP_COMMIT(); cp_wait<1>(); }
        else         { cp_wait<0>(); }
        __syncthreads();

        const uint32_t kvb  = smb + OFF_KV + buf * KVSTRIDE;
        const uint32_t khib = kvb;
        const uint32_t klob = kvb + 16384;
        const uint32_t vhb  = kvb + 32768;
        const float* ksq_s = (const float*)(smc + OFF_KSQ + buf * 512);

        if (kt == 0) {
            #pragma unroll
            for (int kc = 0; kc < 4; kc++) {
                uint32_t kb = kc * 32 + acb;
                uint32_t addr = smb + OFF_Q + arow * 128 + ((((kb >> 4)) ^ (arow & 7)) << 4);
                ldsm4(qh[kc], addr);
                ldsm4(ql[kc], addr + 16384);
            }
        }

        const bool diag = (kt == qt);
        const int m0 = warp * 16 + g8;           // local rows m0, m0+8
        const float qs0 = qsq_s[m0], qs1 = qsq_s[m0 + 8];

        // ======== two 64-key halves, online max/rescale per half ========
        #pragma unroll
        for (int hf = 0; hf < 2; hf++) {
            if (diag && hf * 4 > warp) break;    // whole half masked for warps 0-3

            // ---- S = Q K^T for this half (3 split terms) ----
            float cs[8][4];
            #pragma unroll
            for (int i = 0; i < 8; i++) { cs[i][0] = cs[i][1] = cs[i][2] = cs[i][3] = 0.f; }

            #pragma unroll
            for (int kc = 0; kc < 4; kc++) {
                uint32_t kb = kc * 32 + bcb;
                #pragma unroll
                for (int nf2 = 0; nf2 < 4; nf2++) {
                    if (diag && hf * 4 + nf2 > warp) break;   // masked key chunk
                    int key = (hf * 4 + nf2) * 16 + brow;
                    uint32_t rel = key * 128 + (((kb >> 4) ^ (key & 7)) << 4);
                    uint32_t bkh[4], bkl[4];
                    ldsm4(bkh, khib + rel);                   // Khi
                    ldsm4(bkl, klob + rel);                   // Klo
                    mma_bf16(cs[2 * nf2],     qh[kc], bkh[0], bkh[1]);
                    mma_bf16(cs[2 * nf2 + 1], qh[kc], bkh[2], bkh[3]);
                    mma_bf16(cs[2 * nf2],     ql[kc], bkh[0], bkh[1]);
                    mma_bf16(cs[2 * nf2 + 1], ql[kc], bkh[2], bkh[3]);
                    mma_bf16(cs[2 * nf2],     qh[kc], bkl[0], bkl[1]);
                    mma_bf16(cs[2 * nf2 + 1], qh[kc], bkl[2], bkl[3]);
                }
            }

            // ---- logits + half max ----
            float t0 = -1e30f, t1 = -1e30f;
            #pragma unroll
            for (int nf = 0; nf < 8; nf++) {
                if (diag && hf * 4 + (nf >> 1) > warp) break;
                const int n0 = hf * 64 + nf * 8 + t2;
                const float2 kk = *(const float2*)&ksq_s[n0];
                float l0 = fmaf(L2SCALE, cs[nf][0], -(qs0 + kk.x));
                float l1 = fmaf(L2SCALE, cs[nf][1], -(qs0 + kk.y));
                float l2 = fmaf(L2SCALE, cs[nf][2], -(qs1 + kk.x));
                float l3 = fmaf(L2SCALE, cs[nf][3], -(qs1 + kk.y));
                if (diag) {
                    if (n0     > m0)     l0 = -1e30f;
                    if (n0 + 1 > m0)     l1 = -1e30f;
                    if (n0     > m0 + 8) l2 = -1e30f;
                    if (n0 + 1 > m0 + 8) l3 = -1e30f;
                }
                cs[nf][0] = l0; cs[nf][1] = l1; cs[nf][2] = l2; cs[nf][3] = l3;
                t0 = fmaxf(t0, fmaxf(l0, l1));
                t1 = fmaxf(t1, fmaxf(l2, l3));
            }
            t0 = fmaxf(t0, __shfl_xor_sync(0xffffffffu, t0, 1));
            t0 = fmaxf(t0, __shfl_xor_sync(0xffffffffu, t0, 2));
            t1 = fmaxf(t1, __shfl_xor_sync(0xffffffffu, t1, 1));
            t1 = fmaxf(t1, __shfl_xor_sync(0xffffffffu, t1, 2));
            const float mn0 = fmaxf(m0r, t0), mn1 = fmaxf(m1r, t1);
            const float a0 = exp2f(m0r - mn0), a1 = exp2f(m1r - mn1);
            m0r = mn0; m1r = mn1;
            #pragma unroll
            for (int i = 0; i < 8; i++) {
                co[i][0] *= a0; co[i][1] *= a0; co[i][2] *= a1; co[i][3] *= a1;
            }

            // ---- p = exp2(l - m) via f16x2 MUFU, PV single fp16 term ----
            #pragma unroll
            for (int kc = 0; kc < 4; kc++) {
                if (diag && hf * 4 + kc > warp) break;        // masked key chunk
                uint32_t ah[4];
                #pragma unroll
                for (int h = 0; h < 2; h++) {
                    const int nf = 2 * kc + h;
                    ah[2 * h]     = exp2_f16x2(cs[nf][0] - mn0, cs[nf][1] - mn0);
                    ah[2 * h + 1] = exp2_f16x2(cs[nf][2] - mn1, cs[nf][3] - mn1);
                }
                const int key = (hf * 4 + kc) * 16 + vrow;
                #pragma unroll
                for (int df2 = 0; df2 < 4; df2++) {
                    uint32_t db = df2 * 32 + vcb;
                    uint32_t rel = key * 128 + (((db >> 4) ^ (key & 7)) << 4);
                    uint32_t bv[4];
                    ldsm4t(bv, vhb + rel);                    // V fp16
                    mma_fp16(co[2 * df2],     ah, bv[0], bv[1]);
                    mma_fp16(co[2 * df2 + 1], ah, bv[2], bv[3]);
                }
            }
        }
        __syncthreads();
    }

    // ---- write output: out = co * exp2(m) ----
    const float e0 = exp2f(m0r), e1 = exp2f(m1r);
    const size_t r0 = row0q + warp * 16 + g8;
    const size_t r1 = r0 + 8;
    #pragma unroll
    for (int nf = 0; nf < 8; nf++) {
        const int d = nf * 8 + t2;
        *(float2*)&out[r0 * D_ + d] = make_float2(co[nf][0] * e0, co[nf][1] * e0);
        *(float2*)&out[r1 * D_ + d] = make_float2(co[nf][2] * e1, co[nf][3] * e1);
    }
}

extern "C" void kernel_launch(void* const* d_in, const int* in_sizes, int n_in,
                              void* d_out, int out_size) {
    const float* q = (const float*)d_in[0];
    const float* k = (const float*)d_in[1];
    const float* v = (const float*)d_in[2];
    float* out = (float*)d_out;

    prep_kernel<<<NBHS / 8, 256>>>(q, k, v);

    cudaFuncSetAttribute(rbf_mma_kernel,
                         cudaFuncAttributeMaxDynamicSharedMemorySize, SMEM_BYTES);
    dim3 grid(S_ / 128, B_ * H_);
    rbf_mma_kernel<<<grid, NT, SMEM_BYTES>>>(out);
}

// round 15
// speedup vs baseline: 1.2507x; 1.0420x over previous
#include <cuda_runtime.h>
#include <cuda_bf16.h>
#include <cuda_fp16.h>
#include <cstdint>

// RBF causal attention via mma.sync: bf16 split S, half-tile online max,
// ex2.f16x2 epilogue, single-fp16 PV. 64-row Q tiles, 2 CTAs/SM.
// B=2, H=16, S=2048, D=64, fp32 in/out.

#define B_ 2
#define H_ 16
#define S_ 2048
#define D_ 64
#define SCALE 0.125f
#define LOG2E 1.4426950408889634f
#define L2SCALE (0.25f * LOG2E)
#define NBHS (B_*H_*S_)
#define NBHSD2 (NBHS*32)        // 2-elem vectors per row (D/2 = 32)

// ---- scratch (static device globals; no runtime alloc) ----
__device__ __nv_bfloat162 g_qhi[NBHSD2];
__device__ __nv_bfloat162 g_qlo[NBHSD2];
__device__ __nv_bfloat162 g_khi[NBHSD2];
__device__ __nv_bfloat162 g_klo[NBHSD2];
__device__ __half2        g_vh [NBHSD2];
__device__ float g_qsq[NBHS];   // in log2e units
__device__ float g_ksq[NBHS];   // in log2e units

// ============================ helpers ============================
__device__ __forceinline__ uint32_t smem_u32(const void* p) {
    uint32_t a;
    asm("{ .reg .u64 t; cvta.to.shared.u64 t, %1; cvt.u32.u64 %0, t; }" : "=r"(a) : "l"(p));
    return a;
}
__device__ __forceinline__ void cp16(uint32_t s, const void* g) {
    asm volatile("cp.async.cg.shared.global [%0], [%1], 16;\n" :: "r"(s), "l"(g));
}
#define CP_COMMIT() asm volatile("cp.async.commit_group;\n" ::: "memory")
template <int N>
__device__ __forceinline__ void cp_wait() {
    asm volatile("cp.async.wait_group %0;\n" :: "n"(N) : "memory");
}
__device__ __forceinline__ void ldsm4(uint32_t r[4], uint32_t a) {
    asm volatile("ldmatrix.sync.aligned.m8n8.x4.shared.b16 {%0,%1,%2,%3}, [%4];\n"
        : "=r"(r[0]), "=r"(r[1]), "=r"(r[2]), "=r"(r[3]) : "r"(a));
}
__device__ __forceinline__ void ldsm4t(uint32_t r[4], uint32_t a) {
    asm volatile("ldmatrix.sync.aligned.m8n8.x4.trans.shared.b16 {%0,%1,%2,%3}, [%4];\n"
        : "=r"(r[0]), "=r"(r[1]), "=r"(r[2]), "=r"(r[3]) : "r"(a));
}
__device__ __forceinline__ void mma_bf16(float c[4], const uint32_t a[4],
                                         uint32_t b0, uint32_t b1) {
    asm volatile("mma.sync.aligned.m16n8k16.row.col.f32.bf16.bf16.f32 "
        "{%0,%1,%2,%3}, {%4,%5,%6,%7}, {%8,%9}, {%0,%1,%2,%3};\n"
        : "+f"(c[0]), "+f"(c[1]), "+f"(c[2]), "+f"(c[3])
        : "r"(a[0]), "r"(a[1]), "r"(a[2]), "r"(a[3]), "r"(b0), "r"(b1));
}
__device__ __forceinline__ void mma_fp16(float c[4], const uint32_t a[4],
                                         uint32_t b0, uint32_t b1) {
    asm volatile("mma.sync.aligned.m16n8k16.row.col.f32.f16.f16.f32 "
        "{%0,%1,%2,%3}, {%4,%5,%6,%7}, {%8,%9}, {%0,%1,%2,%3};\n"
        : "+f"(c[0]), "+f"(c[1]), "+f"(c[2]), "+f"(c[3])
        : "r"(a[0]), "r"(a[1]), "r"(a[2]), "r"(a[3]), "r"(b0), "r"(b1));
}
// pack 2 f32 -> f16x2 (lo = x0), then 2^x elementwise on MUFU (one op per pair)
__device__ __forceinline__ uint32_t exp2_f16x2(float x0, float x1) {
    uint32_t c, r;
    asm("cvt.rn.f16x2.f32 %0, %1, %2;" : "=r"(c) : "f"(x1), "f"(x0));
    asm("ex2.approx.f16x2 %0, %1;" : "=r"(r) : "r"(c));
    return r;
}

// ============================ prepass ============================
__global__ __launch_bounds__(256)
void prep_kernel(const float* __restrict__ q, const float* __restrict__ k,
                 const float* __restrict__ v) {
    int r   = blockIdx.x * 8 + (threadIdx.x >> 5);
    int lid = threadIdx.x & 31;
    size_t e2 = (size_t)r * 32 + lid;

    float2 x = ((const float2*)q)[e2];
    __nv_bfloat162 h = __floats2bfloat162_rn(x.x, x.y);
    float2 hf = __bfloat1622float2(h);
    g_qhi[e2] = h;
    g_qlo[e2] = __floats2bfloat162_rn(x.x - hf.x, x.y - hf.y);
    float s = x.x * x.x + x.y * x.y;
    #pragma unroll
    for (int o = 16; o; o >>= 1) s += __shfl_xor_sync(0xffffffffu, s, o);
    if (!lid) g_qsq[r] = SCALE * LOG2E * s;

    x = ((const float2*)k)[e2];
    h = __floats2bfloat162_rn(x.x, x.y);
    hf = __bfloat1622float2(h);
    g_khi[e2] = h;
    g_klo[e2] = __floats2bfloat162_rn(x.x - hf.x, x.y - hf.y);
    s = x.x * x.x + x.y * x.y;
    #pragma unroll
    for (int o = 16; o; o >>= 1) s += __shfl_xor_sync(0xffffffffu, s, o);
    if (!lid) g_ksq[r] = SCALE * LOG2E * s;

    x = ((const float2*)v)[e2];
    g_vh[e2] = __floats2half2_rn(x.x, x.y);
}

// ============================ main kernel ============================
#define NT 128
#define OFF_KV  0              // per buf: Khi,Klo,Vh (16KB each)
#define KVSTRIDE 49152
#define OFF_KSQ 98304          // 512B per buf x2
#define SMEM_BYTES 99328

__global__ __launch_bounds__(NT, 2)
void rbf_mma_kernel(float* __restrict__ out) {
    extern __shared__ char smc[];
    const uint32_t smb = smem_u32(smc);
    const int tid = threadIdx.x, lane = tid & 31, warp = tid >> 5;
    const int bh = blockIdx.y;
    const int qt = (int)gridDim.x - 1 - (int)blockIdx.x;   // heavy tiles first
    const size_t row0q = (size_t)bh * S_ + (size_t)qt * 64;

    auto prefetch = [&](int kt2, int buf) {
        const size_t row0k = (size_t)bh * S_ + (size_t)kt2 * 128;
        const char* ga[3] = { (const char*)(g_khi + row0k * 32),
                              (const char*)(g_klo + row0k * 32),
                              (const char*)(g_vh  + row0k * 32) };
        const uint32_t bb = smb + OFF_KV + buf * KVSTRIDE;
        #pragma unroll
        for (int a = 0; a < 3; a++)
            #pragma unroll
            for (int i = 0; i < 8; i++) {
                int idx = tid + NT * i;          // 0..1023 16B chunks
                int row = idx >> 3, c = idx & 7;
                cp16(bb + a * 16384 + row * 128 + ((c ^ (row & 7)) << 4), ga[a] + idx * 16);
            }
        if (tid < 32) cp16(smb + OFF_KSQ + buf * 512 + tid * 16, g_ksq + row0k + tid * 4);
    };

    prefetch(0, 0);
    CP_COMMIT();

    // per-thread fragment coordinates
    const int g8 = lane >> 2;                    // 0..7
    const int t4 = lane & 3;
    const int t2 = t4 * 2;                       // 0,2,4,6
    const int brow = (lane & 7) + (lane >> 4) * 8;       // K ldmatrix row offset
    const int bcb  = ((lane >> 3) & 1) * 16;             // K k-byte half
    const int vrow = (lane & 7) + ((lane >> 3) & 1) * 8; // V ldmatrix row offset
    const int vcb  = (lane >> 4) * 16;                   // V d-byte half

    // ---- Q fragments + qsq straight from global (once) ----
    uint32_t qh[4][4], ql[4][4];
    #pragma unroll
    for (int kc = 0; kc < 4; kc++)
        #pragma unroll
        for (int r = 0; r < 4; r++) {
            size_t row = row0q + warp * 16 + g8 + (r & 1) * 8;
            int col2 = kc * 8 + (r >> 1) * 4 + t4;
            qh[kc][r] = *(const uint32_t*)&g_qhi[row * 32 + col2];
            ql[kc][r] = *(const uint32_t*)&g_qlo[row * 32 + col2];
        }
    const float qs0 = g_qsq[row0q + warp * 16 + g8];
    const float qs1 = g_qsq[row0q + warp * 16 + g8 + 8];
    const int am = qt * 64 + warp * 16 + g8;     // absolute q-row (sequence index)

    float co[8][4];
    #pragma unroll
    for (int i = 0; i < 8; i++) { co[i][0] = co[i][1] = co[i][2] = co[i][3] = 0.f; }
    float m0r = -1e30f, m1r = -1e30f;            // running row maxima (log2 units)

    const int ktmax = qt >> 1;
    const int qodd  = qt & 1;

    for (int kt = 0; kt <= ktmax; kt++) {
        const int buf = kt & 1;
        if (kt < ktmax) { prefetch(kt + 1, buf ^ 1); CP_COMMIT(); cp_wait<1>(); }
        else            { cp_wait<0>(); }
        __syncthreads();

        const uint32_t kvb  = smb + OFF_KV + buf * KVSTRIDE;
        const uint32_t khib = kvb;
        const uint32_t klob = kvb + 16384;
        const uint32_t vhb  = kvb + 32768;
        const float* ksq_s = (const float*)(smc + OFF_KSQ + buf * 512);

        const bool isdiag = (kt == ktmax);

        // ======== two 64-key halves, online max/rescale per half ========
        #pragma unroll
        for (int hf = 0; hf < 2; hf++) {
            if (isdiag && !qodd && hf == 1) break;         // above diagonal
            const bool hmask = isdiag && (hf == qodd);     // half containing diagonal

            // ---- S = Q K^T for this half (3 split terms) ----
            float cs[8][4];
            #pragma unroll
            for (int i = 0; i < 8; i++) { cs[i][0] = cs[i][1] = cs[i][2] = cs[i][3] = 0.f; }

            #pragma unroll
            for (int kc = 0; kc < 4; kc++) {
                uint32_t kb = kc * 32 + bcb;
                #pragma unroll
                for (int nf2 = 0; nf2 < 4; nf2++) {
                    if (hmask && nf2 > warp) break;        // masked key chunk
                    int key = (hf * 4 + nf2) * 16 + brow;
                    uint32_t rel = key * 128 + (((kb >> 4) ^ (key & 7)) << 4);
                    uint32_t bkh[4], bkl[4];
                    ldsm4(bkh, khib + rel);                // Khi
                    ldsm4(bkl, klob + rel);                // Klo
                    mma_bf16(cs[2 * nf2],     qh[kc], bkh[0], bkh[1]);
                    mma_bf16(cs[2 * nf2 + 1], qh[kc], bkh[2], bkh[3]);
                    mma_bf16(cs[2 * nf2],     ql[kc], bkh[0], bkh[1]);
                    mma_bf16(cs[2 * nf2 + 1], ql[kc], bkh[2], bkh[3]);
                    mma_bf16(cs[2 * nf2],     qh[kc], bkl[0], bkl[1]);
                    mma_bf16(cs[2 * nf2 + 1], qh[kc], bkl[2], bkl[3]);
                }
            }

            // ---- logits + half max ----
            float t0 = -1e30f, t1 = -1e30f;
            #pragma unroll
            for (int nf = 0; nf < 8; nf++) {
                if (hmask && (nf >> 1) > warp) break;
                const int nl = hf * 64 + nf * 8 + t2;      // key index in k-tile
                const int an = kt * 128 + nl;              // absolute key index
                const float2 kk = *(const float2*)&ksq_s[nl];
                float l0 = fmaf(L2SCALE, cs[nf][0], -(qs0 + kk.x));
                float l1 = fmaf(L2SCALE, cs[nf][1], -(qs0 + kk.y));
                float l2 = fmaf(L2SCALE, cs[nf][2], -(qs1 + kk.x));
                float l3 = fmaf(L2SCALE, cs[nf][3], -(qs1 + kk.y));
                if (hmask) {
                    if (an     > am)     l0 = -1e30f;
                    if (an + 1 > am)     l1 = -1e30f;
                    if (an     > am + 8) l2 = -1e30f;
                    if (an + 1 > am + 8) l3 = -1e30f;
                }
                cs[nf][0] = l0; cs[nf][1] = l1; cs[nf][2] = l2; cs[nf][3] = l3;
                t0 = fmaxf(t0, fmaxf(l0, l1));
                t1 = fmaxf(t1, fmaxf(l2, l3));
            }
            t0 = fmaxf(t0, __shfl_xor_sync(0xffffffffu, t0, 1));
            t0 = fmaxf(t0, __shfl_xor_sync(0xffffffffu, t0, 2));
            t1 = fmaxf(t1, __shfl_xor_sync(0xffffffffu, t1, 1));
            t1 = fmaxf(t1, __shfl_xor_sync(0xffffffffu, t1, 2));
            const float mn0 = fmaxf(m0r, t0), mn1 = fmaxf(m1r, t1);
            const float a0 = exp2f(m0r - mn0), a1 = exp2f(m1r - mn1);
            m0r = mn0; m1r = mn1;
            #pragma unroll
            for (int i = 0; i < 8; i++) {
                co[i][0] *= a0; co[i][1] *= a0; co[i][2] *= a1; co[i][3] *= a1;
            }

            // ---- p = exp2(l - m) via f16x2 MUFU, PV single fp16 term ----
            #pragma unroll
            for (int kc = 0; kc < 4; kc++) {
                if (hmask && kc > warp) break;             // masked key chunk
                uint32_t ah[4];
                #pragma unroll
                for (int h = 0; h < 2; h++) {
                    const int nf = 2 * kc + h;
                    ah[2 * h]     = exp2_f16x2(cs[nf][0] - mn0, cs[nf][1] - mn0);
                    ah[2 * h + 1] = exp2_f16x2(cs[nf][2] - mn1, cs[nf][3] - mn1);
                }
                const int key = (hf * 4 + kc) * 16 + vrow;
                #pragma unroll
                for (int df2 = 0; df2 < 4; df2++) {
                    uint32_t db = df2 * 32 + vcb;
                    uint32_t rel = key * 128 + (((db >> 4) ^ (key & 7)) << 4);
                    uint32_t bv[4];
                    ldsm4t(bv, vhb + rel);                 // V fp16
                    mma_fp16(co[2 * df2],     ah, bv[0], bv[1]);
                    mma_fp16(co[2 * df2 + 1], ah, bv[2], bv[3]);
                }
            }
        }
        __syncthreads();
    }

    // ---- write output: out = co * exp2(m) ----
    const float e0 = exp2f(m0r), e1 = exp2f(m1r);
    const size_t r0 = row0q + warp * 16 + g8;
    const size_t r1 = r0 + 8;
    #pragma unroll
    for (int nf = 0; nf < 8; nf++) {
        const int d = nf * 8 + t2;
        *(float2*)&out[r0 * D_ + d] = make_float2(co[nf][0] * e0, co[nf][1] * e0);
        *(float2*)&out[r1 * D_ + d] = make_float2(co[nf][2] * e1, co[nf][3] * e1);
    }
}

extern "C" void kernel_launch(void* const* d_in, const int* in_sizes, int n_in,
                              void* d_out, int out_size) {
    const float* q = (const float*)d_in[0];
    const float* k = (const float*)d_in[1];
    const float* v = (const float*)d_in[2];
    float* out = (float*)d_out;

    prep_kernel<<<NBHS / 8, 256>>>(q, k, v);

    cudaFuncSetAttribute(rbf_mma_kernel,
                         cudaFuncAttributeMaxDynamicSharedMemorySize, SMEM_BYTES);
    dim3 grid(S_ / 64, B_ * H_);
    rbf_mma_kernel<<<grid, NT, SMEM_BYTES>>>(out);
}

// round 16
// speedup vs baseline: 1.3275x; 1.0614x over previous
#include <cuda_runtime.h>
#include <cuda_bf16.h>
#include <cuda_fp16.h>
#include <cstdint>

// RBF causal attention via mma.sync: bf16 split S, 64-key-block online max,
// ex2.f16x2 epilogue, single-fp16 PV. 64-row Q tiles, 3 CTAs/SM.
// B=2, H=16, S=2048, D=64, fp32 in/out.

#define B_ 2
#define H_ 16
#define S_ 2048
#define D_ 64
#define SCALE 0.125f
#define LOG2E 1.4426950408889634f
#define L2SCALE (0.25f * LOG2E)
#define NBHS (B_*H_*S_)
#define NBHSD2 (NBHS*32)        // 2-elem vectors per row (D/2 = 32)

// ---- scratch (static device globals; no runtime alloc) ----
__device__ __nv_bfloat162 g_qhi[NBHSD2];
__device__ __nv_bfloat162 g_qlo[NBHSD2];
__device__ __nv_bfloat162 g_khi[NBHSD2];
__device__ __nv_bfloat162 g_klo[NBHSD2];
__device__ __half2        g_vh [NBHSD2];
__device__ float g_qsq[NBHS];   // in log2e units
__device__ float g_ksq[NBHS];   // in log2e units

// ============================ helpers ============================
__device__ __forceinline__ uint32_t smem_u32(const void* p) {
    uint32_t a;
    asm("{ .reg .u64 t; cvta.to.shared.u64 t, %1; cvt.u32.u64 %0, t; }" : "=r"(a) : "l"(p));
    return a;
}
__device__ __forceinline__ void cp16(uint32_t s, const void* g) {
    asm volatile("cp.async.cg.shared.global [%0], [%1], 16;\n" :: "r"(s), "l"(g));
}
#define CP_COMMIT() asm volatile("cp.async.commit_group;\n" ::: "memory")
template <int N>
__device__ __forceinline__ void cp_wait() {
    asm volatile("cp.async.wait_group %0;\n" :: "n"(N) : "memory");
}
__device__ __forceinline__ void ldsm4(uint32_t r[4], uint32_t a) {
    asm volatile("ldmatrix.sync.aligned.m8n8.x4.shared.b16 {%0,%1,%2,%3}, [%4];\n"
        : "=r"(r[0]), "=r"(r[1]), "=r"(r[2]), "=r"(r[3]) : "r"(a));
}
__device__ __forceinline__ void ldsm4t(uint32_t r[4], uint32_t a) {
    asm volatile("ldmatrix.sync.aligned.m8n8.x4.trans.shared.b16 {%0,%1,%2,%3}, [%4];\n"
        : "=r"(r[0]), "=r"(r[1]), "=r"(r[2]), "=r"(r[3]) : "r"(a));
}
__device__ __forceinline__ void mma_bf16(float c[4], const uint32_t a[4],
                                         uint32_t b0, uint32_t b1) {
    asm volatile("mma.sync.aligned.m16n8k16.row.col.f32.bf16.bf16.f32 "
        "{%0,%1,%2,%3}, {%4,%5,%6,%7}, {%8,%9}, {%0,%1,%2,%3};\n"
        : "+f"(c[0]), "+f"(c[1]), "+f"(c[2]), "+f"(c[3])
        : "r"(a[0]), "r"(a[1]), "r"(a[2]), "r"(a[3]), "r"(b0), "r"(b1));
}
__device__ __forceinline__ void mma_fp16(float c[4], const uint32_t a[4],
                                         uint32_t b0, uint32_t b1) {
    asm volatile("mma.sync.aligned.m16n8k16.row.col.f32.f16.f16.f32 "
        "{%0,%1,%2,%3}, {%4,%5,%6,%7}, {%8,%9}, {%0,%1,%2,%3};\n"
        : "+f"(c[0]), "+f"(c[1]), "+f"(c[2]), "+f"(c[3])
        : "r"(a[0]), "r"(a[1]), "r"(a[2]), "r"(a[3]), "r"(b0), "r"(b1));
}
// pack 2 f32 -> f16x2 (lo = x0), then 2^x elementwise on MUFU (one op per pair)
__device__ __forceinline__ uint32_t exp2_f16x2(float x0, float x1) {
    uint32_t c, r;
    asm("cvt.rn.f16x2.f32 %0, %1, %2;" : "=r"(c) : "f"(x1), "f"(x0));
    asm("ex2.approx.f16x2 %0, %1;" : "=r"(r) : "r"(c));
    return r;
}

// ============================ prepass ============================
__global__ __launch_bounds__(256)
void prep_kernel(const float* __restrict__ q, const float* __restrict__ k,
                 const float* __restrict__ v) {
    int r   = blockIdx.x * 8 + (threadIdx.x >> 5);
    int lid = threadIdx.x & 31;
    size_t e2 = (size_t)r * 32 + lid;

    float2 x = ((const float2*)q)[e2];
    __nv_bfloat162 h = __floats2bfloat162_rn(x.x, x.y);
    float2 hf = __bfloat1622float2(h);
    g_qhi[e2] = h;
    g_qlo[e2] = __floats2bfloat162_rn(x.x - hf.x, x.y - hf.y);
    float s = x.x * x.x + x.y * x.y;
    #pragma unroll
    for (int o = 16; o; o >>= 1) s += __shfl_xor_sync(0xffffffffu, s, o);
    if (!lid) g_qsq[r] = SCALE * LOG2E * s;

    x = ((const float2*)k)[e2];
    h = __floats2bfloat162_rn(x.x, x.y);
    hf = __bfloat1622float2(h);
    g_khi[e2] = h;
    g_klo[e2] = __floats2bfloat162_rn(x.x - hf.x, x.y - hf.y);
    s = x.x * x.x + x.y * x.y;
    #pragma unroll
    for (int o = 16; o; o >>= 1) s += __shfl_xor_sync(0xffffffffu, s, o);
    if (!lid) g_ksq[r] = SCALE * LOG2E * s;

    x = ((const float2*)v)[e2];
    g_vh[e2] = __floats2half2_rn(x.x, x.y);
}

// ============================ main kernel ============================
#define NT 128
// per 64-key buffer: Khi 8KB @0, Klo 8KB @8192, V 8KB @16384
#define KBSTRIDE 24576
#define OFF_KSQ 49152          // 256B per buf x2
#define SMEM_BYTES 49664

__global__ __launch_bounds__(NT, 3)
void rbf_mma_kernel(float* __restrict__ out) {
    extern __shared__ char smc[];
    const uint32_t smb = smem_u32(smc);
    const int tid = threadIdx.x, lane = tid & 31, warp = tid >> 5;
    const int bh = blockIdx.y;
    const int qt = (int)gridDim.x - 1 - (int)blockIdx.x;   // heavy tiles first
    const size_t row0q = (size_t)bh * S_ + (size_t)qt * 64;

    // prefetch one 64-key block (Khi, Klo, V + ksq) into buffer buf
    auto prefetch = [&](int kb2, int buf) {
        const size_t row0k = (size_t)bh * S_ + (size_t)kb2 * 64;
        const char* ga[3] = { (const char*)(g_khi + row0k * 32),
                              (const char*)(g_klo + row0k * 32),
                              (const char*)(g_vh  + row0k * 32) };
        const uint32_t bb = smb + buf * KBSTRIDE;
        #pragma unroll
        for (int a = 0; a < 3; a++)
            #pragma unroll
            for (int i = 0; i < 4; i++) {
                int idx = tid + NT * i;          // 0..511 16B chunks (64 rows x 8)
                int row = idx >> 3, c = idx & 7;
                cp16(bb + a * 8192 + row * 128 + ((c ^ (row & 7)) << 4), ga[a] + idx * 16);
            }
        if (tid < 16) cp16(smb + OFF_KSQ + buf * 256 + tid * 16, g_ksq + row0k + tid * 4);
    };

    prefetch(0, 0);
    CP_COMMIT();

    // per-thread fragment coordinates
    const int g8 = lane >> 2;                    // 0..7
    const int t4 = lane & 3;
    const int t2 = t4 * 2;                       // 0,2,4,6
    const int brow = (lane & 7) + (lane >> 4) * 8;       // K ldmatrix row offset
    const int bcb  = ((lane >> 3) & 1) * 16;             // K k-byte half
    const int vrow = (lane & 7) + ((lane >> 3) & 1) * 8; // V ldmatrix row offset
    const int vcb  = (lane >> 4) * 16;                   // V d-byte half

    // ---- Q fragments + qsq straight from global (once) ----
    uint32_t qh[4][4], ql[4][4];
    #pragma unroll
    for (int kc = 0; kc < 4; kc++)
        #pragma unroll
        for (int r = 0; r < 4; r++) {
            size_t row = row0q + warp * 16 + g8 + (r & 1) * 8;
            int col2 = kc * 8 + (r >> 1) * 4 + t4;
            qh[kc][r] = *(const uint32_t*)&g_qhi[row * 32 + col2];
            ql[kc][r] = *(const uint32_t*)&g_qlo[row * 32 + col2];
        }
    const float qs0 = g_qsq[row0q + warp * 16 + g8];
    const float qs1 = g_qsq[row0q + warp * 16 + g8 + 8];
    const int am = qt * 64 + warp * 16 + g8;     // absolute q-row (sequence index)

    float co[8][4];
    #pragma unroll
    for (int i = 0; i < 8; i++) { co[i][0] = co[i][1] = co[i][2] = co[i][3] = 0.f; }
    float m0r = -1e30f, m1r = -1e30f;            // running row maxima (log2 units)

    for (int kb = 0; kb <= qt; kb++) {
        const int buf = kb & 1;
        if (kb < qt) { prefetch(kb + 1, buf ^ 1); CP_COMMIT(); cp_wait<1>(); }
        else         { cp_wait<0>(); }
        __syncthreads();

        const uint32_t khib = smb + buf * KBSTRIDE;
        const uint32_t klob = khib + 8192;
        const uint32_t vhb  = khib + 16384;
        const float* ksq_s = (const float*)(smc + OFF_KSQ + buf * 256);
        const bool hmask = (kb == qt);           // block containing the diagonal

        // ---- S = Q K^T (3 split terms), warp stripe 16 x 64 ----
        float cs[8][4];
        #pragma unroll
        for (int i = 0; i < 8; i++) { cs[i][0] = cs[i][1] = cs[i][2] = cs[i][3] = 0.f; }

        #pragma unroll
        for (int kc = 0; kc < 4; kc++) {
            uint32_t kb2 = kc * 32 + bcb;
            #pragma unroll
            for (int nf2 = 0; nf2 < 4; nf2++) {
                if (hmask && nf2 > warp) break;  // masked key chunk
                int key = nf2 * 16 + brow;
                uint32_t rel = key * 128 + (((kb2 >> 4) ^ (key & 7)) << 4);
                uint32_t bkh[4], bkl[4];
                ldsm4(bkh, khib + rel);          // Khi
                ldsm4(bkl, klob + rel);          // Klo
                mma_bf16(cs[2 * nf2],     qh[kc], bkh[0], bkh[1]);
                mma_bf16(cs[2 * nf2 + 1], qh[kc], bkh[2], bkh[3]);
                mma_bf16(cs[2 * nf2],     ql[kc], bkh[0], bkh[1]);
                mma_bf16(cs[2 * nf2 + 1], ql[kc], bkh[2], bkh[3]);
                mma_bf16(cs[2 * nf2],     qh[kc], bkl[0], bkl[1]);
                mma_bf16(cs[2 * nf2 + 1], qh[kc], bkl[2], bkl[3]);
            }
        }

        // ---- logits + block max ----
        float t0 = -1e30f, t1 = -1e30f;
        #pragma unroll
        for (int nf = 0; nf < 8; nf++) {
            if (hmask && (nf >> 1) > warp) break;
            const int nl = nf * 8 + t2;          // key index in block
            const int an = kb * 64 + nl;         // absolute key index
            const float2 kk = *(const float2*)&ksq_s[nl];
            float l0 = fmaf(L2SCALE, cs[nf][0], -(qs0 + kk.x));
            float l1 = fmaf(L2SCALE, cs[nf][1], -(qs0 + kk.y));
            float l2 = fmaf(L2SCALE, cs[nf][2], -(qs1 + kk.x));
            float l3 = fmaf(L2SCALE, cs[nf][3], -(qs1 + kk.y));
            if (hmask) {
                if (an     > am)     l0 = -1e30f;
                if (an + 1 > am)     l1 = -1e30f;
                if (an     > am + 8) l2 = -1e30f;
                if (an + 1 > am + 8) l3 = -1e30f;
            }
            cs[nf][0] = l0; cs[nf][1] = l1; cs[nf][2] = l2; cs[nf][3] = l3;
            t0 = fmaxf(t0, fmaxf(l0, l1));
            t1 = fmaxf(t1, fmaxf(l2, l3));
        }
        t0 = fmaxf(t0, __shfl_xor_sync(0xffffffffu, t0, 1));
        t0 = fmaxf(t0, __shfl_xor_sync(0xffffffffu, t0, 2));
        t1 = fmaxf(t1, __shfl_xor_sync(0xffffffffu, t1, 1));
        t1 = fmaxf(t1, __shfl_xor_sync(0xffffffffu, t1, 2));
        const float mn0 = fmaxf(m0r, t0), mn1 = fmaxf(m1r, t1);
        const float a0 = exp2f(m0r - mn0), a1 = exp2f(m1r - mn1);
        m0r = mn0; m1r = mn1;
        #pragma unroll
        for (int i = 0; i < 8; i++) {
            co[i][0] *= a0; co[i][1] *= a0; co[i][2] *= a1; co[i][3] *= a1;
        }

        // ---- p = exp2(l - m) via f16x2 MUFU, PV single fp16 term ----
        #pragma unroll
        for (int kc = 0; kc < 4; kc++) {
            if (hmask && kc > warp) break;       // masked key chunk
            uint32_t ah[4];
            #pragma unroll
            for (int h = 0; h < 2; h++) {
                const int nf = 2 * kc + h;
                ah[2 * h]     = exp2_f16x2(cs[nf][0] - mn0, cs[nf][1] - mn0);
                ah[2 * h + 1] = exp2_f16x2(cs[nf][2] - mn1, cs[nf][3] - mn1);
            }
            const int key = kc * 16 + vrow;
            #pragma unroll
            for (int df2 = 0; df2 < 4; df2++) {
                uint32_t db = df2 * 32 + vcb;
                uint32_t rel = key * 128 + (((db >> 4) ^ (key & 7)) << 4);
                uint32_t bv[4];
                ldsm4t(bv, vhb + rel);           // V fp16
                mma_fp16(co[2 * df2],     ah, bv[0], bv[1]);
                mma_fp16(co[2 * df2 + 1], ah, bv[2], bv[3]);
            }
        }
        __syncthreads();
    }

    // ---- write output: out = co * exp2(m) ----
    const float e0 = exp2f(m0r), e1 = exp2f(m1r);
    const size_t r0 = row0q + warp * 16 + g8;
    const size_t r1 = r0 + 8;
    #pragma unroll
    for (int nf = 0; nf < 8; nf++) {
        const int d = nf * 8 + t2;
        *(float2*)&out[r0 * D_ + d] = make_float2(co[nf][0] * e0, co[nf][1] * e0);
        *(float2*)&out[r1 * D_ + d] = make_float2(co[nf][2] * e1, co[nf][3] * e1);
    }
}

extern "C" void kernel_launch(void* const* d_in, const int* in_sizes, int n_in,
                              void* d_out, int out_size) {
    const float* q = (const float*)d_in[0];
    const float* k = (const float*)d_in[1];
    const float* v = (const float*)d_in[2];
    float* out = (float*)d_out;

    prep_kernel<<<NBHS / 8, 256>>>(q, k, v);

    cudaFuncSetAttribute(rbf_mma_kernel,
                         cudaFuncAttributeMaxDynamicSharedMemorySize, SMEM_BYTES);
    dim3 grid(S_ / 64, B_ * H_);
    rbf_mma_kernel<<<grid, NT, SMEM_BYTES>>>(out);
}